// round 4
// baseline (speedup 1.0000x reference)
#include <cuda_runtime.h>
#include <cuda_bf16.h>
#include <mma.h>
#include <cstdint>
#include <cstddef>

using namespace nvcuda;

#define CC 256
#define PP 4096

// ---------------- scratch (device globals: no allocation allowed) ----------------
static __device__ float g_X  [(size_t)262144 * CC];  // LN(original_features)
static __device__ float g_G  [PP * CC];              // LN(segment mean of dg)
static __device__ float g_ATT[PP * CC];              // attn (= residual)
static __device__ float g_Y  [PP * CC];              // LN(attn)
static __device__ float g_H  [PP * CC];              // relu(y@W1.T+b1)
static __device__ float g_DG [PP * CC];              // dg
static __device__ float g_G2 [PP * CC];              // dg@Wf2.T + fuse_b
static __device__ float g_WVO[CC * CC];              // out_proj_w @ Wv
static __device__ float g_BVO[CC];                   // out_proj_w @ bv + bo

// ---------------- fold Wvo = Wo @ Wv, bvo = Wo @ bv + bo ----------------
__global__ void make_wvo(const float* __restrict__ Wo, const float* __restrict__ Wv,
                         const float* __restrict__ bv, const float* __restrict__ bo,
                         float* __restrict__ Wvo, float* __restrict__ bvo)
{
    const int i = blockIdx.x;     // output row
    const int t = threadIdx.x;    // output col
    __shared__ float sWo[CC];
    __shared__ float red[CC];
    sWo[t] = Wo[i * CC + t];
    __syncthreads();
    float s = 0.f;
    #pragma unroll 8
    for (int j = 0; j < CC; j++) s += sWo[j] * Wv[j * CC + t];
    Wvo[i * CC + t] = s;
    red[t] = sWo[t] * bv[t];
    __syncthreads();
    for (int o = 128; o > 0; o >>= 1) {
        if (t < o) red[t] += red[t + o];
        __syncthreads();
    }
    if (t == 0) bvo[i] = red[0] + bo[i];
}

// ---------------- segment mean (sorted batch) fused with dg LayerNorm ----------------
__global__ void seg_mean_ln(const float* __restrict__ dg, const int* __restrict__ batch, int n,
                            const float* __restrict__ w, const float* __restrict__ b,
                            float* __restrict__ gout)
{
    const int p = blockIdx.x;
    const int t = threadIdx.x;
    __shared__ int sb[2];
    __shared__ float red[CC];
    if (t < 2) {
        int target = p + t;
        int lo = 0, hi = n;
        while (lo < hi) {
            int mid = (lo + hi) >> 1;
            if (batch[mid] < target) lo = mid + 1; else hi = mid;
        }
        sb[t] = lo;
    }
    __syncthreads();
    const int start = sb[0], end = sb[1];
    float s = 0.f;
    for (int r = start; r < end; r++) s += dg[(size_t)r * CC + t];
    const int cnt = end - start;
    float mv = (cnt > 0) ? s / (float)cnt : 0.f;

    // block LayerNorm over the 256-wide mean vector (one value per thread)
    red[t] = mv; __syncthreads();
    for (int o = 128; o > 0; o >>= 1) { if (t < o) red[t] += red[t + o]; __syncthreads(); }
    const float mu = red[0] * (1.f / CC);
    __syncthreads();
    red[t] = mv * mv; __syncthreads();
    for (int o = 128; o > 0; o >>= 1) { if (t < o) red[t] += red[t + o]; __syncthreads(); }
    const float var = red[0] * (1.f / CC) - mu * mu;
    const float rstd = rsqrtf(var + 1e-5f);
    gout[(size_t)p * CC + t] = (mv - mu) * rstd * w[t] + b[t];
}

// ---------------- warp-per-row LayerNorm (C = 256) ----------------
__global__ void ln_rows(const float* __restrict__ in, const float* __restrict__ w,
                        const float* __restrict__ b, float* __restrict__ out, int rows)
{
    const int warp = blockIdx.x * (blockDim.x >> 5) + (threadIdx.x >> 5);
    if (warp >= rows) return;
    const int lane = threadIdx.x & 31;
    const float* rp = in + (size_t)warp * CC;
    float v[8];
    float s = 0.f, s2 = 0.f;
    #pragma unroll
    for (int i = 0; i < 8; i++) {
        v[i] = rp[lane + 32 * i];
        s  += v[i];
        s2 += v[i] * v[i];
    }
    #pragma unroll
    for (int o = 16; o > 0; o >>= 1) {
        s  += __shfl_xor_sync(0xFFFFFFFFu, s,  o);
        s2 += __shfl_xor_sync(0xFFFFFFFFu, s2, o);
    }
    const float mu  = s * (1.f / CC);
    const float var = s2 * (1.f / CC) - mu * mu;
    const float rstd = rsqrtf(var + 1e-5f);
    float* op = out + (size_t)warp * CC;
    #pragma unroll
    for (int i = 0; i < 8; i++) {
        const int c = lane + 32 * i;
        op[c] = (v[i] - mu) * rstd * w[c] + b[c];
    }
}

// ---------------- tf32 tensor-core GEMM: C[m,n] = sum_k A[m,k] * B[n,k] + epilogue ----------------
// A row-major [M, 256], B row-major [Ncols, K] with row stride ldb (weights, i.e. W so A@W.T),
// output row stride 256. K fixed = 256.
constexpr int BM = 128, BN = 64, BK = 32;
constexpr int LA = BK + 4;   // 36 (padded smem ld, multiple of 4)
constexpr int LC = BN + 4;   // 68

template<bool RELU, bool BIG>
__global__ __launch_bounds__(256)
void gemm_tf32(const float* __restrict__ A,
               const float* __restrict__ B, int ldb,
               float* __restrict__ C,
               const float* __restrict__ bias,   // nullable, indexed by col
               const float* __restrict__ res,    // nullable, [M,256] add (pre-relu path unused)
               const int*   __restrict__ batch,  // BIG only
               const float* __restrict__ g2,     // BIG only, [P,256]
               const float* __restrict__ xres)   // BIG only, [M,256] post-relu add
{
    __shared__ __align__(16) float smem[BM * LC];   // 34816 B, reused for tiles then epilogue
    float* As = smem;                // BM*LA = 4608 floats
    float* Bs = smem + BM * LA;      // BN*LA = 2304 floats (total 6912 <= 8704)

    const int tid = threadIdx.x;
    const int warpId = tid >> 5;
    const int wm = warpId & 3;       // warp row block (32 rows each)
    const int wn = warpId >> 2;      // warp col block (32 cols each)
    const size_t gm = (size_t)blockIdx.y * BM;
    const int gn = blockIdx.x * BN;

    wmma::fragment<wmma::accumulator, 16, 16, 8, float> acc[2][2];
    #pragma unroll
    for (int i = 0; i < 2; i++)
        #pragma unroll
        for (int j = 0; j < 2; j++)
            wmma::fill_fragment(acc[i][j], 0.0f);

    const int lr = tid >> 3;          // 0..31
    const int lc = (tid & 7) << 2;    // 0,4,...,28

    for (int k0 = 0; k0 < CC; k0 += BK) {
        __syncthreads();
        #pragma unroll
        for (int p = 0; p < 4; p++) {
            const int r = lr + 32 * p;
            float4 v = *reinterpret_cast<const float4*>(A + (gm + r) * CC + k0 + lc);
            float4 t;
            t.x = wmma::__float_to_tf32(v.x);
            t.y = wmma::__float_to_tf32(v.y);
            t.z = wmma::__float_to_tf32(v.z);
            t.w = wmma::__float_to_tf32(v.w);
            *reinterpret_cast<float4*>(&As[r * LA + lc]) = t;
        }
        #pragma unroll
        for (int p = 0; p < 2; p++) {
            const int r = lr + 32 * p;
            float4 v = *reinterpret_cast<const float4*>(B + (size_t)(gn + r) * ldb + k0 + lc);
            float4 t;
            t.x = wmma::__float_to_tf32(v.x);
            t.y = wmma::__float_to_tf32(v.y);
            t.z = wmma::__float_to_tf32(v.z);
            t.w = wmma::__float_to_tf32(v.w);
            *reinterpret_cast<float4*>(&Bs[r * LA + lc]) = t;
        }
        __syncthreads();
        #pragma unroll
        for (int kk = 0; kk < BK; kk += 8) {
            wmma::fragment<wmma::matrix_a, 16, 16, 8, wmma::precision::tf32, wmma::row_major> af[2];
            wmma::fragment<wmma::matrix_b, 16, 16, 8, wmma::precision::tf32, wmma::col_major> bf[2];
            #pragma unroll
            for (int i = 0; i < 2; i++)
                wmma::load_matrix_sync(af[i], &As[(wm * 32 + 16 * i) * LA + kk], LA);
            #pragma unroll
            for (int j = 0; j < 2; j++)
                wmma::load_matrix_sync(bf[j], &Bs[(wn * 32 + 16 * j) * LA + kk], LA);
            #pragma unroll
            for (int i = 0; i < 2; i++)
                #pragma unroll
                for (int j = 0; j < 2; j++)
                    wmma::mma_sync(acc[i][j], af[i], bf[j], acc[i][j]);
        }
    }
    __syncthreads();
    #pragma unroll
    for (int i = 0; i < 2; i++)
        #pragma unroll
        for (int j = 0; j < 2; j++)
            wmma::store_matrix_sync(&smem[(wm * 32 + 16 * i) * LC + wn * 32 + 16 * j],
                                    acc[i][j], LC, wmma::mem_row_major);
    __syncthreads();

    const int ec = tid & 63;   // 0..63
    const int er = tid >> 6;   // 0..3
    #pragma unroll 4
    for (int r = er; r < BM; r += 4) {
        float c = smem[r * LC + ec];
        const size_t row = gm + r;
        const int col = gn + ec;
        if (bias) c += bias[col];
        if (BIG) {
            c += g2[(size_t)batch[row] * CC + col];
            c = fmaxf(c, 0.0f);
            c += xres[row * CC + col];
        } else {
            if (res) c += res[row * CC + col];
            if (RELU) c = fmaxf(c, 0.0f);
        }
        C[row * CC + col] = c;
    }
}

// ---------------- launcher ----------------
extern "C" void kernel_launch(void* const* d_in, const int* in_sizes, int n_in,
                              void* d_out, int out_size)
{
    const float* orig       = (const float*)d_in[0];
    const float* dgf        = (const float*)d_in[1];
    const float* node_w     = (const float*)d_in[2];
    const float* node_b     = (const float*)d_in[3];
    const float* dg_w       = (const float*)d_in[4];
    const float* dg_b       = (const float*)d_in[5];
    const float* in_proj_w  = (const float*)d_in[6];
    const float* in_proj_b  = (const float*)d_in[7];
    const float* out_proj_w = (const float*)d_in[8];
    const float* out_proj_b = (const float*)d_in[9];
    const float* ffn_w      = (const float*)d_in[10];
    const float* ffn_b      = (const float*)d_in[11];
    const float* l1w        = (const float*)d_in[12];
    const float* l1b        = (const float*)d_in[13];
    const float* l2w        = (const float*)d_in[14];
    const float* l2b        = (const float*)d_in[15];
    const float* fuse_w     = (const float*)d_in[16];   // [256, 512] row-major
    const float* fuse_b     = (const float*)d_in[17];
    const int*   batch      = (const int*)d_in[18];
    const int n = in_sizes[0] / CC;                      // 262144

    float *X, *G, *ATT, *Y, *H, *DG, *G2, *WVO, *BVO;
    cudaGetSymbolAddress((void**)&X,   g_X);
    cudaGetSymbolAddress((void**)&G,   g_G);
    cudaGetSymbolAddress((void**)&ATT, g_ATT);
    cudaGetSymbolAddress((void**)&Y,   g_Y);
    cudaGetSymbolAddress((void**)&H,   g_H);
    cudaGetSymbolAddress((void**)&DG,  g_DG);
    cudaGetSymbolAddress((void**)&G2,  g_G2);
    cudaGetSymbolAddress((void**)&WVO, g_WVO);
    cudaGetSymbolAddress((void**)&BVO, g_BVO);

    const dim3 sg(CC / BN, PP / BM);   // small-GEMM grid: (4, 32)

    // 1) fold out_proj @ V-slice of in_proj
    make_wvo<<<CC, CC>>>(out_proj_w, in_proj_w + 2 * CC * CC, in_proj_b + 2 * CC,
                         out_proj_b, WVO, BVO);
    // 2) segment mean over sorted batch + dg LayerNorm -> G
    seg_mean_ln<<<PP, CC>>>(dgf, batch, n, dg_w, dg_b, G);
    // 3) attn = G @ Wvo.T + bvo
    gemm_tf32<false, false><<<sg, 256>>>(G, WVO, CC, ATT, BVO, nullptr, nullptr, nullptr, nullptr);
    // 4) Y = LN(attn)
    ln_rows<<<PP / 8, 256>>>(ATT, ffn_w, ffn_b, Y, PP);
    // 5) H = relu(Y @ lin1.T + b1)
    gemm_tf32<true, false><<<sg, 256>>>(Y, l1w, CC, H, l1b, nullptr, nullptr, nullptr, nullptr);
    // 6) DG = H @ lin2.T + b2 + attn
    gemm_tf32<false, false><<<sg, 256>>>(H, l2w, CC, DG, l2b, ATT, nullptr, nullptr, nullptr);
    // 7) G2 = DG @ fuse_w[:,256:].T + fuse_b   (per-patch half of the fuse GEMM)
    gemm_tf32<false, false><<<sg, 256>>>(DG, fuse_w + CC, 2 * CC, G2, fuse_b,
                                         nullptr, nullptr, nullptr, nullptr);
    // 8) X = LN(orig)
    ln_rows<<<n / 8, 256>>>(orig, node_w, node_b, X, n);
    // 9) out = relu(X @ fuse_w[:,:256].T + G2[batch]) + X
    gemm_tf32<false, true><<<dim3(CC / BN, n / BM), 256>>>(X, fuse_w, 2 * CC, (float*)d_out,
                                                           nullptr, nullptr, batch, G2, X);
}